// round 1
// baseline (speedup 1.0000x reference)
#include <cuda_runtime.h>

namespace {
constexpr int kB   = 64;
constexpr int kN   = 883;
constexpr int kT   = 12;
constexpr int kTN  = 16;
constexpr int kTOD = 288;
constexpr int kP   = kB * kN;              // 56512 (b,n) pairs
constexpr unsigned FM = 0xffffffffu;

__device__ __forceinline__ float rsum16(float v) {
    v += __shfl_xor_sync(FM, v, 8, 16);
    v += __shfl_xor_sync(FM, v, 4, 16);
    v += __shfl_xor_sync(FM, v, 2, 16);
    v += __shfl_xor_sync(FM, v, 1, 16);
    return v;
}
__device__ __forceinline__ float rmax16(float v) {
    v = fmaxf(v, __shfl_xor_sync(FM, v, 8, 16));
    v = fmaxf(v, __shfl_xor_sync(FM, v, 4, 16));
    v = fmaxf(v, __shfl_xor_sync(FM, v, 2, 16));
    v = fmaxf(v, __shfl_xor_sync(FM, v, 1, 16));
    return v;
}
} // namespace

__global__ void __launch_bounds__(256) mode_att_kernel(
    const float* __restrict__ enc,
    const int*   __restrict__ xm,
    const float* __restrict__ dec,
    const float* __restrict__ kb,
    const float* __restrict__ vb,
    const float* __restrict__ aw,
    const float* __restrict__ ab,
    float*       __restrict__ out)
{
    const int warp = (blockIdx.x * blockDim.x + threadIdx.x) >> 5;
    if (warp >= kP) return;
    const int lane = threadIdx.x & 31;
    const int b = warp / kN;
    const int n = warp - b * kN;
    const int t = xm[b * 2];            // x_mark_enc[b,0,0]
    const int y = lane & 15;

    // Lanes 0-15 load K rows, lanes 16-31 load the matching V rows.
    const float* __restrict__ bank = (lane < 16) ? kb : vb;
    const float* __restrict__ row  =
        bank + ((size_t)((n * kTOD + t) * kTN + y)) * kT;

    float rr[12];
    {
        float4 a = *(const float4*)(row);
        float4 c = *(const float4*)(row + 4);
        float4 e = *(const float4*)(row + 8);
        rr[0]=a.x; rr[1]=a.y; rr[2]=a.z; rr[3]=a.w;
        rr[4]=c.x; rr[5]=c.y; rr[6]=c.z; rr[7]=c.w;
        rr[8]=e.x; rr[9]=e.y; rr[10]=e.z; rr[11]=e.w;
    }

    float qq[12];
    {
        const float* __restrict__ qp = enc + (size_t)warp * kT;
        float4 a = *(const float4*)(qp);
        float4 c = *(const float4*)(qp + 4);
        float4 e = *(const float4*)(qp + 8);
        qq[0]=a.x; qq[1]=a.y; qq[2]=a.z; qq[3]=a.w;
        qq[4]=c.x; qq[5]=c.y; qq[6]=c.z; qq[7]=c.w;
        qq[8]=e.x; qq[9]=e.y; qq[10]=e.z; qq[11]=e.w;
    }

    // Per-key distance (meaningful on lanes 0-15; upper half computes garbage
    // that never crosses the 16-lane shuffle boundary).
    float dd = 0.f;
#pragma unroll
    for (int d = 0; d < 12; ++d) {
        float df = qq[d] - rr[d];
        dd = fmaf(df, df, dd);
    }
    const float dist = sqrtf(dd);

    // --- first softmax over TN=16 keys ---
    const float s16  = rsum16(dist);
    const float mean = s16 * (1.0f / 16.0f);
    const float dv   = dist - mean;
    const float var  = rsum16(dv * dv) * (1.0f / 15.0f);
    const float istd = 10.0f / (sqrtf(var) + 1e-6f);
    const float sc   = (mean - dist) * istd;
    const float mx   = rmax16(sc);
    const float ex   = expf(sc - mx);
    const float es   = rsum16(ex);
    const float prob = ex / es;

    // lane 16+y fetches prob of key y (lanes 0-15 fetch their own)
    const float av = __shfl_sync(FM, prob, y);

    // att_out = sum_y prob_y * V[y][:]  (reduced across the upper 16 lanes)
    float o[12];
#pragma unroll
    for (int d = 0; d < 12; ++d) o[d] = av * rr[d];
#pragma unroll
    for (int m = 8; m >= 1; m >>= 1) {
#pragma unroll
        for (int d = 0; d < 12; ++d)
            o[d] += __shfl_xor_sync(FM, o[d], m, 16);
    }

    // --- second softmax over 17 keys (17th key = Q + 0.1, dist = sqrt(0.12)) ---
    const float d16    = 0.34641016151377545871f;           // sqrt(12 * 0.1^2)
    const float mean17 = (s16 + d16) * (1.0f / 17.0f);
    const float dv2    = dist - mean17;
    const float c16    = d16  - mean17;
    const float var17  = (rsum16(dv2 * dv2) + c16 * c16) * (1.0f / 16.0f);
    const float istd2  = 10.0f / (sqrtf(var17) + 1e-6f);
    const float s2     = (mean17 - dist) * istd2;
    const float s2_16  = (mean17 - d16)  * istd2;
    const float mx2    = fmaxf(rmax16(s2), s2_16);
    const float e2     = expf(s2   - mx2);
    const float e16    = expf(s2_16 - mx2);
    const float inv    = 1.0f / (rsum16(e2) + e16);

    const float* __restrict__ awp = aw + n * (kTN + 1);
    float w = rsum16((e2 * inv) * awp[y]);
    w += (e16 * inv) * awp[16] + ab[n];
    w = __shfl_sync(FM, w, 0);          // broadcast valid value from lane 0

    // --- blend and write (lanes 16-18 hold the fully reduced o[]) ---
    const float omw   = 1.0f - w;
    const size_t base = (size_t)warp * kT;
    if (lane == 16) {
        float4 d4 = *(const float4*)(dec + base);
        float4 r4 = make_float4(fmaf(omw, o[0], w * d4.x),
                                fmaf(omw, o[1], w * d4.y),
                                fmaf(omw, o[2], w * d4.z),
                                fmaf(omw, o[3], w * d4.w));
        *(float4*)(out + base) = r4;
    } else if (lane == 17) {
        float4 d4 = *(const float4*)(dec + base + 4);
        float4 r4 = make_float4(fmaf(omw, o[4], w * d4.x),
                                fmaf(omw, o[5], w * d4.y),
                                fmaf(omw, o[6], w * d4.z),
                                fmaf(omw, o[7], w * d4.w));
        *(float4*)(out + base + 4) = r4;
    } else if (lane == 18) {
        float4 d4 = *(const float4*)(dec + base + 8);
        float4 r4 = make_float4(fmaf(omw, o[8],  w * d4.x),
                                fmaf(omw, o[9],  w * d4.y),
                                fmaf(omw, o[10], w * d4.z),
                                fmaf(omw, o[11], w * d4.w));
        *(float4*)(out + base + 8) = r4;
    }
}

extern "C" void kernel_launch(void* const* d_in, const int* in_sizes, int n_in,
                              void* d_out, int out_size) {
    const float* enc = (const float*)d_in[0];
    const int*   xm  = (const int*)  d_in[1];
    const float* dec = (const float*)d_in[2];
    const float* kb  = (const float*)d_in[3];
    const float* vb  = (const float*)d_in[4];
    const float* aw  = (const float*)d_in[5];
    const float* ab  = (const float*)d_in[6];
    float*       out = (float*)d_out;

    const int warps_per_block = 256 / 32;                 // 8
    const int blocks = (kP + warps_per_block - 1) / warps_per_block;  // 7064
    mode_att_kernel<<<blocks, 256>>>(enc, xm, dec, kb, vb, aw, ab, out);
}

// round 2
// speedup vs baseline: 1.5838x; 1.5838x over previous
#include <cuda_runtime.h>

namespace {
constexpr int kB   = 64;
constexpr int kN   = 883;
constexpr int kT   = 12;
constexpr int kTN  = 16;
constexpr int kTOD = 288;
constexpr int kP   = kB * kN;              // 56512 (b,n) pairs, 2 per warp
constexpr unsigned FM = 0xffffffffu;

__device__ __forceinline__ float rsum16(float v) {
    v += __shfl_xor_sync(FM, v, 8, 16);
    v += __shfl_xor_sync(FM, v, 4, 16);
    v += __shfl_xor_sync(FM, v, 2, 16);
    v += __shfl_xor_sync(FM, v, 1, 16);
    return v;
}
__device__ __forceinline__ float rmax16(float v) {
    v = fmaxf(v, __shfl_xor_sync(FM, v, 8, 16));
    v = fmaxf(v, __shfl_xor_sync(FM, v, 4, 16));
    v = fmaxf(v, __shfl_xor_sync(FM, v, 2, 16));
    v = fmaxf(v, __shfl_xor_sync(FM, v, 1, 16));
    return v;
}
} // namespace

__global__ void __launch_bounds__(256) mode_att_kernel(
    const float* __restrict__ enc,
    const int*   __restrict__ xm,
    const float* __restrict__ dec,
    const float* __restrict__ kb,
    const float* __restrict__ vb,
    const float* __restrict__ aw,
    const float* __restrict__ ab,
    float*       __restrict__ out)
{
    const int warp = (blockIdx.x * blockDim.x + threadIdx.x) >> 5;
    const int lane = threadIdx.x & 31;
    const int y    = lane & 15;
    const int p    = warp * 2 + (lane >> 4);   // problem index for this half-warp
    if (p >= kP) return;

    const int b = p / kN;
    const int n = p - b * kN;
    const int t = __ldg(xm + b * 2);           // x_mark_enc[b,0,0]

    const size_t rbase = ((size_t)((n * kTOD + t) * kTN + y)) * kT;
    const float* __restrict__ kr = kb + rbase;
    const float* __restrict__ vr = vb + rbase;

    // Issue all loads up front for MLP.
    float4 k0 = *(const float4*)(kr);
    float4 k1 = *(const float4*)(kr + 4);
    float4 k2 = *(const float4*)(kr + 8);
    float4 v0 = *(const float4*)(vr);
    float4 v1 = *(const float4*)(vr + 4);
    float4 v2 = *(const float4*)(vr + 8);

    const float* __restrict__ qp = enc + (size_t)p * kT;
    float4 q0 = *(const float4*)(qp);
    float4 q1 = *(const float4*)(qp + 4);
    float4 q2 = *(const float4*)(qp + 8);

    // Per-key squared distance.
    float dd = 0.f, df;
    df = q0.x - k0.x; dd = fmaf(df, df, dd);
    df = q0.y - k0.y; dd = fmaf(df, df, dd);
    df = q0.z - k0.z; dd = fmaf(df, df, dd);
    df = q0.w - k0.w; dd = fmaf(df, df, dd);
    df = q1.x - k1.x; dd = fmaf(df, df, dd);
    df = q1.y - k1.y; dd = fmaf(df, df, dd);
    df = q1.z - k1.z; dd = fmaf(df, df, dd);
    df = q1.w - k1.w; dd = fmaf(df, df, dd);
    df = q2.x - k2.x; dd = fmaf(df, df, dd);
    df = q2.y - k2.y; dd = fmaf(df, df, dd);
    df = q2.z - k2.z; dd = fmaf(df, df, dd);
    df = q2.w - k2.w; dd = fmaf(df, df, dd);
    const float dist = sqrtf(dd);

    // --- first softmax over TN=16 keys ---
    const float s16  = rsum16(dist);
    const float mean = s16 * (1.0f / 16.0f);
    const float dv   = dist - mean;
    const float var  = rsum16(dv * dv) * (1.0f / 15.0f);
    const float istd = __fdividef(10.0f, sqrtf(var) + 1e-6f);
    const float sc   = (mean - dist) * istd;
    const float mx   = rmax16(sc);
    const float ex   = __expf(sc - mx);
    const float es   = rsum16(ex);
    const float prob = __fdividef(ex, es);

    // att_out partials: this lane's key prob times its V row.
    float o[12];
    o[0] = prob * v0.x; o[1]  = prob * v0.y; o[2]  = prob * v0.z; o[3]  = prob * v0.w;
    o[4] = prob * v1.x; o[5]  = prob * v1.y; o[6]  = prob * v1.z; o[7]  = prob * v1.w;
    o[8] = prob * v2.x; o[9]  = prob * v2.y; o[10] = prob * v2.z; o[11] = prob * v2.w;
#pragma unroll
    for (int m = 8; m >= 1; m >>= 1) {
#pragma unroll
        for (int d = 0; d < 12; ++d)
            o[d] += __shfl_xor_sync(FM, o[d], m, 16);
    }

    // --- second softmax over 17 keys (17th key = Q + 0.1, dist = sqrt(12*0.01)) ---
    const float d16    = 0.34641016151377545871f;
    const float mean17 = (s16 + d16) * (1.0f / 17.0f);
    const float dv2    = dist - mean17;
    const float c16    = d16  - mean17;
    const float var17  = (rsum16(dv2 * dv2) + c16 * c16) * (1.0f / 16.0f);
    const float istd2  = __fdividef(10.0f, sqrtf(var17) + 1e-6f);
    const float s2     = (mean17 - dist) * istd2;
    const float s2_16  = (mean17 - d16)  * istd2;
    const float mx2    = fmaxf(rmax16(s2), s2_16);
    const float e2     = __expf(s2    - mx2);
    const float e16    = __expf(s2_16 - mx2);
    const float inv    = __fdividef(1.0f, rsum16(e2) + e16);

    const float* __restrict__ awp = aw + n * (kTN + 1);
    float w = rsum16((e2 * inv) * __ldg(awp + y));
    w += (e16 * inv) * __ldg(awp + 16) + __ldg(ab + n);
    // rsum16 butterfly leaves the full sum in every lane of the group.

    // --- blend and write: lanes y=0,1,2 of each group write one float4 each ---
    if (y < 3) {
        const float omw = 1.0f - w;
        const size_t base = (size_t)p * kT + y * 4;
        float4 d4 = *(const float4*)(dec + base);
        const int j = y * 4;
        float4 r4 = make_float4(fmaf(omw, o[j + 0], w * d4.x),
                                fmaf(omw, o[j + 1], w * d4.y),
                                fmaf(omw, o[j + 2], w * d4.z),
                                fmaf(omw, o[j + 3], w * d4.w));
        *(float4*)(out + base) = r4;
    }
}

extern "C" void kernel_launch(void* const* d_in, const int* in_sizes, int n_in,
                              void* d_out, int out_size) {
    const float* enc = (const float*)d_in[0];
    const int*   xm  = (const int*)  d_in[1];
    const float* dec = (const float*)d_in[2];
    const float* kb  = (const float*)d_in[3];
    const float* vb  = (const float*)d_in[4];
    const float* aw  = (const float*)d_in[5];
    const float* ab  = (const float*)d_in[6];
    float*       out = (float*)d_out;

    const int problems_per_block = 16;                 // 8 warps * 2
    const int blocks = (kP + problems_per_block - 1) / problems_per_block;  // 3532
    mode_att_kernel<<<blocks, 256>>>(enc, xm, dec, kb, vb, aw, ab, out);
}